// round 3
// baseline (speedup 1.0000x reference)
#include <cuda_runtime.h>
#include <cuda_bf16.h>
#include <math.h>

// Problem constants (fixed by the dataset)
#define NN 100000          // nodes
#define EE 1600000         // edges
#define D_IN 128
#define D_H  64
#define D_OUT 32

// ---------------- device scratch (static globals; no allocation) -------------
__device__ int   g_deg[NN];
__device__ int   g_row_ptr[NN + 1];
__device__ int   g_cursor[NN];
__device__ int   g_col[EE];
__device__ float g_dinv[NN];
__device__ int   g_blocksums[512];

__device__ float g_W1c[128 * 128];   // rows 0..63 = W1_l, 64..127 = W1_r  (K=128 contiguous)
__device__ float g_W2c[64 * 64];     // rows 0..31 = W2_l, 32..63 = W2_r   (K=64 contiguous)

__device__ float g_yz1[(size_t)NN * 128];  // per node: [0..63]=x@W1_l^T, [64..127]=x@W1_r^T
__device__ float g_h  [(size_t)NN * 64];   // relu hidden
__device__ float g_yz2[(size_t)NN * 64];   // per node: [0..31]=h@W2_l^T, [32..63]=h@W2_r^T

// ---------------- small utility kernels ----------------
__global__ void k_zero_deg(int n) {
    int i = blockIdx.x * blockDim.x + threadIdx.x;
    if (i < n) g_deg[i] = 0;
}

// edge_index delivered as int32: [0..E) = src, [E..2E) = dst
__global__ void k_deg(const int* __restrict__ ei, int E, int n) {
    int e = blockIdx.x * blockDim.x + threadIdx.x;
    if (e < E) {
        unsigned dst = (unsigned)ei[E + e];
        if (dst < (unsigned)n) atomicAdd(&g_deg[dst], 1);
    }
}

// block-wise scan -> exclusive result per element, block totals out
__global__ void k_scan_a(int n) {
    __shared__ int s[512];
    int gid = blockIdx.x * 512 + threadIdx.x;
    int v = (gid < n) ? g_deg[gid] : 0;
    s[threadIdx.x] = v;
    __syncthreads();
    for (int off = 1; off < 512; off <<= 1) {
        int t = (threadIdx.x >= off) ? s[threadIdx.x - off] : 0;
        __syncthreads();
        s[threadIdx.x] += t;
        __syncthreads();
    }
    if (gid < n) g_row_ptr[gid] = s[threadIdx.x] - v;   // exclusive within block
    if (threadIdx.x == 511) g_blocksums[blockIdx.x] = s[511];
}

__global__ void k_scan_b(int nblocks) {
    __shared__ int s[512];
    int v = (threadIdx.x < nblocks) ? g_blocksums[threadIdx.x] : 0;
    s[threadIdx.x] = v;
    __syncthreads();
    for (int off = 1; off < 512; off <<= 1) {
        int t = (threadIdx.x >= off) ? s[threadIdx.x - off] : 0;
        __syncthreads();
        s[threadIdx.x] += t;
        __syncthreads();
    }
    if (threadIdx.x < nblocks) g_blocksums[threadIdx.x] = s[threadIdx.x] - v; // exclusive
}

__global__ void k_scan_c(int n, int E) {
    int gid = blockIdx.x * 512 + threadIdx.x;
    if (gid < n) {
        int rp = g_row_ptr[gid] + g_blocksums[blockIdx.x];
        g_row_ptr[gid] = rp;
        g_cursor[gid]  = rp;
        float d = (float)g_deg[gid];
        g_dinv[gid] = 1.0f / fmaxf(d, 1.0f);
    }
    if (gid == 0) g_row_ptr[n] = E;
}

__global__ void k_fill(const int* __restrict__ ei, int E, int n) {
    int e = blockIdx.x * blockDim.x + threadIdx.x;
    if (e < E) {
        unsigned src = (unsigned)ei[e];
        unsigned dst = (unsigned)ei[E + e];
        if (dst < (unsigned)n && src < (unsigned)n) {
            int pos = atomicAdd(&g_cursor[dst], 1);
            g_col[pos] = (int)src;
        }
    }
}

__global__ void k_pack_w(const float* __restrict__ W1l, const float* __restrict__ W1r,
                         const float* __restrict__ W2l, const float* __restrict__ W2r) {
    int t = blockIdx.x * blockDim.x + threadIdx.x;
    if (t < 64 * 128)            g_W1c[t] = W1l[t];
    else if (t < 128 * 128)      g_W1c[t] = W1r[t - 64 * 128];
    if (t < 32 * 64)             g_W2c[t] = W2l[t];
    else if (t < 64 * 64)        g_W2c[t] = W2r[t - 32 * 64];
}

// ---------------- tiled GEMM: C[m][n] = sum_k A[m*K+k] * B[n*K+k] ------------
// (A row-major MxK, B row-major NxK -> C = A * B^T), BN must equal N.
// LAYER selects which __device__ globals to use for A/B/C (no host symbol API).
template <int LAYER, int BM, int BN, int BK, int TM, int TN>
__global__ void gemm_tn(const float* __restrict__ A_ext, int M, int N, int K) {
    constexpr int THREADS = (BM / TM) * (BN / TN);
    __shared__ float As[BK][BM];
    __shared__ float Bs[BK][BN];

    const float* __restrict__ A = (LAYER == 1) ? A_ext : g_h;
    const float* __restrict__ B = (LAYER == 1) ? g_W1c : g_W2c;
    float* __restrict__ C       = (LAYER == 1) ? g_yz1 : g_yz2;

    const int tid = threadIdx.x;
    const int bm0 = blockIdx.x * BM;
    const int tx = tid % (BN / TN);
    const int ty = tid / (BN / TN);

    float acc[TM][TN];
#pragma unroll
    for (int i = 0; i < TM; i++)
#pragma unroll
        for (int j = 0; j < TN; j++) acc[i][j] = 0.0f;

    for (int k0 = 0; k0 < K; k0 += BK) {
        // load A tile (BM x BK), transposed into As[k][m]
#pragma unroll
        for (int i = tid; i < BM * BK / 4; i += THREADS) {
            int row = i / (BK / 4);
            int c4 = (i % (BK / 4)) * 4;
            int grow = bm0 + row;
            float4 v = make_float4(0.f, 0.f, 0.f, 0.f);
            if (grow < M) v = *(const float4*)(A + (size_t)grow * K + k0 + c4);
            As[c4 + 0][row] = v.x;
            As[c4 + 1][row] = v.y;
            As[c4 + 2][row] = v.z;
            As[c4 + 3][row] = v.w;
        }
        // load B tile (BN x BK), transposed into Bs[k][n]; B always in-bounds
#pragma unroll
        for (int i = tid; i < BN * BK / 4; i += THREADS) {
            int row = i / (BK / 4);
            int c4 = (i % (BK / 4)) * 4;
            float4 v = *(const float4*)(B + (size_t)row * K + k0 + c4);
            Bs[c4 + 0][row] = v.x;
            Bs[c4 + 1][row] = v.y;
            Bs[c4 + 2][row] = v.z;
            Bs[c4 + 3][row] = v.w;
        }
        __syncthreads();

#pragma unroll
        for (int k = 0; k < BK; k++) {
            float a[TM], b[TN];
#pragma unroll
            for (int i = 0; i < TM; i++) a[i] = As[k][ty * TM + i];
#pragma unroll
            for (int j = 0; j < TN; j++) b[j] = Bs[k][tx * TN + j];
#pragma unroll
            for (int i = 0; i < TM; i++)
#pragma unroll
                for (int j = 0; j < TN; j++) acc[i][j] = fmaf(a[i], b[j], acc[i][j]);
        }
        __syncthreads();
    }

#pragma unroll
    for (int i = 0; i < TM; i++) {
        int grow = bm0 + ty * TM + i;
        if (grow < M) {
#pragma unroll
            for (int j = 0; j < TN; j++) {
                C[(size_t)grow * N + tx * TN + j] = acc[i][j];
            }
        }
    }
}

// ---------------- layer 1 aggregation + epilogue (relu) ----------------
// one warp per node; lanes cover 64 cols as (lane, lane+32)
__global__ void k_agg1(const float* __restrict__ b1, int n) {
    int warp = (blockIdx.x * blockDim.x + threadIdx.x) >> 5;
    int lane = threadIdx.x & 31;
    if (warp >= n) return;
    int e0 = g_row_ptr[warp];
    int e1 = g_row_ptr[warp + 1];
    float a0 = 0.f, a1 = 0.f;
    for (int e = e0; e < e1; e++) {
        int s = g_col[e];
        const float* r = g_yz1 + (size_t)s * 128;
        a0 += r[lane];
        a1 += r[lane + 32];
    }
    float di = g_dinv[warp];
    const float* self = g_yz1 + (size_t)warp * 128;
    float v0 = a0 * di + b1[lane]      + self[64 + lane];
    float v1 = a1 * di + b1[lane + 32] + self[96 + lane];
    g_h[(size_t)warp * 64 + lane]      = fmaxf(v0, 0.f);
    g_h[(size_t)warp * 64 + lane + 32] = fmaxf(v1, 0.f);
}

// ---------------- layer 2 aggregation + epilogue (log_softmax) ----------------
// one warp per node; lane = output column (32 cols)
__global__ void k_agg2(const float* __restrict__ b2, float* __restrict__ out, int n) {
    int warp = (blockIdx.x * blockDim.x + threadIdx.x) >> 5;
    int lane = threadIdx.x & 31;
    if (warp >= n) return;
    int e0 = g_row_ptr[warp];
    int e1 = g_row_ptr[warp + 1];
    float a = 0.f;
    for (int e = e0; e < e1; e++) {
        int s = g_col[e];
        a += g_yz2[(size_t)s * 64 + lane];
    }
    float di = g_dinv[warp];
    float val = a * di + b2[lane] + g_yz2[(size_t)warp * 64 + 32 + lane];

    // log_softmax across 32 lanes
    float m = val;
#pragma unroll
    for (int off = 16; off >= 1; off >>= 1) m = fmaxf(m, __shfl_xor_sync(0xffffffffu, m, off));
    float ex = __expf(val - m);
    float s = ex;
#pragma unroll
    for (int off = 16; off >= 1; off >>= 1) s += __shfl_xor_sync(0xffffffffu, s, off);
    out[(size_t)warp * 32 + lane] = val - m - logf(s);
}

// ---------------- launch ----------------
extern "C" void kernel_launch(void* const* d_in, const int* in_sizes, int n_in,
                              void* d_out, int out_size) {
    const float* x   = (const float*)d_in[0];
    const int*   ei  = (const int*)d_in[1];    // int32 per harness dtype set
    const float* W1l = (const float*)d_in[2];
    const float* b1  = (const float*)d_in[3];
    const float* W1r = (const float*)d_in[4];
    const float* W2l = (const float*)d_in[5];
    const float* b2  = (const float*)d_in[6];
    const float* W2r = (const float*)d_in[7];
    float*       out = (float*)d_out;

    const int n = in_sizes[0] / D_IN;       // 100000
    const int E = in_sizes[1] / 2;          // 1600000

    // 1) degree histogram
    k_zero_deg<<<(n + 255) / 256, 256>>>(n);
    k_deg<<<(E + 255) / 256, 256>>>(ei, E, n);

    // 2) exclusive scan -> row_ptr, cursor, dinv
    int scan_blocks = (n + 511) / 512;      // 196
    k_scan_a<<<scan_blocks, 512>>>(n);
    k_scan_b<<<1, 512>>>(scan_blocks);
    k_scan_c<<<scan_blocks, 512>>>(n, E);

    // 3) CSR column fill
    k_fill<<<(E + 255) / 256, 256>>>(ei, E, n);

    // 4) pack weights
    k_pack_w<<<(128 * 128 + 255) / 256, 256>>>(W1l, W1r, W2l, W2r);

    // 5) GEMM 1: yz1[n,128] = x[n,128] @ W1c^T  (cols 0..63 = l-path, 64..127 = r-path)
    gemm_tn<1, 64, 128, 16, 4, 8><<<(n + 63) / 64, 256>>>(x, n, 128, 128);

    // 6) aggregation + relu -> h
    k_agg1<<<(n * 32 + 255) / 256, 256>>>(b1, n);

    // 7) GEMM 2: yz2[n,64] = h[n,64] @ W2c^T (cols 0..31 = l-path, 32..63 = r-path)
    gemm_tn<2, 64, 64, 16, 4, 4><<<(n + 63) / 64, 256>>>(nullptr, n, 64, 64);

    // 8) aggregation + log_softmax -> out
    k_agg2<<<(n * 32 + 255) / 256, 256>>>(b2, out, n);
}

// round 5
// speedup vs baseline: 1.6756x; 1.6756x over previous
#include <cuda_runtime.h>
#include <cuda_bf16.h>
#include <math.h>
#include <stdint.h>

#define NN 100000
#define EE 1600000
#define D_IN 128
#define D_H  64
#define D_OUT 32

// ---------------- device scratch ----------------
__device__ int   g_deg[NN];
__device__ int   g_row_ptr[NN + 1];
__device__ int   g_cursor[NN];
__device__ int   g_col[EE];
__device__ float g_dinv[NN];
__device__ int   g_blocksums[512];

__device__ float g_W1c[128 * 128];   // rows 0..63 = W1_l, 64..127 = W1_r
__device__ float g_W2c[64 * 64];     // rows 0..31 = W2_l, 32..63 = W2_r

__device__ float g_yz1[(size_t)NN * 128];
__device__ float g_h  [(size_t)NN * 64];
__device__ float g_yz2[(size_t)NN * 64];

// ---------------- PTX helpers (base-arch only) ----------------
__device__ __forceinline__ uint32_t smem_u32(const void* p) {
    uint32_t a;
    asm("{ .reg .u64 t; cvta.to.shared.u64 t, %1; cvt.u32.u64 %0, t; }" : "=r"(a) : "l"(p));
    return a;
}

#define LDSM_X4(r0, r1, r2, r3, addr) \
    asm volatile("ldmatrix.sync.aligned.m8n8.x4.shared.b16 {%0,%1,%2,%3}, [%4];" \
                 : "=r"(r0), "=r"(r1), "=r"(r2), "=r"(r3) : "r"(addr))
#define LDSM_X2(r0, r1, addr) \
    asm volatile("ldmatrix.sync.aligned.m8n8.x2.shared.b16 {%0,%1}, [%2];" \
                 : "=r"(r0), "=r"(r1) : "r"(addr))
#define MMA_BF16(c, a0, a1, a2, a3, b0, b1) \
    asm volatile("mma.sync.aligned.m16n8k16.row.col.f32.bf16.bf16.f32 " \
                 "{%0,%1,%2,%3}, {%4,%5,%6,%7}, {%8,%9}, {%0,%1,%2,%3};" \
                 : "+f"((c)[0]), "+f"((c)[1]), "+f"((c)[2]), "+f"((c)[3]) \
                 : "r"(a0), "r"(a1), "r"(a2), "r"(a3), "r"(b0), "r"(b1))

// split a pair of floats into bf16-hi pair + bf16-lo (residual) pair
__device__ __forceinline__ uint32_t pack_hilo(float a, float b, uint32_t& lo_out) {
    __nv_bfloat16 ha = __float2bfloat16(a), hb = __float2bfloat16(b);
    __nv_bfloat16 la = __float2bfloat16(a - __bfloat162float(ha));
    __nv_bfloat16 lb = __float2bfloat16(b - __bfloat162float(hb));
    __nv_bfloat162 h; h.x = ha; h.y = hb;
    __nv_bfloat162 l; l.x = la; l.y = lb;
    lo_out = *(uint32_t*)&l;
    return *(uint32_t*)&h;
}

// ---------------- small utility kernels ----------------
__global__ void k_zero_deg(int n) {
    int i = blockIdx.x * blockDim.x + threadIdx.x;
    if (i < n) g_deg[i] = 0;
}

__global__ void k_deg(const int* __restrict__ ei, int E, int n) {
    int e = blockIdx.x * blockDim.x + threadIdx.x;
    if (e < E) {
        unsigned dst = (unsigned)ei[E + e];
        if (dst < (unsigned)n) atomicAdd(&g_deg[dst], 1);
    }
}

__global__ void k_scan_a(int n) {
    __shared__ int s[512];
    int gid = blockIdx.x * 512 + threadIdx.x;
    int v = (gid < n) ? g_deg[gid] : 0;
    s[threadIdx.x] = v;
    __syncthreads();
    for (int off = 1; off < 512; off <<= 1) {
        int t = (threadIdx.x >= off) ? s[threadIdx.x - off] : 0;
        __syncthreads();
        s[threadIdx.x] += t;
        __syncthreads();
    }
    if (gid < n) g_row_ptr[gid] = s[threadIdx.x] - v;
    if (threadIdx.x == 511) g_blocksums[blockIdx.x] = s[511];
}

__global__ void k_scan_b(int nblocks) {
    __shared__ int s[512];
    int v = (threadIdx.x < nblocks) ? g_blocksums[threadIdx.x] : 0;
    s[threadIdx.x] = v;
    __syncthreads();
    for (int off = 1; off < 512; off <<= 1) {
        int t = (threadIdx.x >= off) ? s[threadIdx.x - off] : 0;
        __syncthreads();
        s[threadIdx.x] += t;
        __syncthreads();
    }
    if (threadIdx.x < nblocks) g_blocksums[threadIdx.x] = s[threadIdx.x] - v;
}

__global__ void k_scan_c(int n, int E) {
    int gid = blockIdx.x * 512 + threadIdx.x;
    if (gid < n) {
        int rp = g_row_ptr[gid] + g_blocksums[blockIdx.x];
        g_row_ptr[gid] = rp;
        g_cursor[gid]  = rp;
        float d = (float)g_deg[gid];
        g_dinv[gid] = 1.0f / fmaxf(d, 1.0f);
    }
    if (gid == 0) g_row_ptr[n] = E;
}

__global__ void k_fill(const int* __restrict__ ei, int E, int n) {
    int e = blockIdx.x * blockDim.x + threadIdx.x;
    if (e < E) {
        unsigned src = (unsigned)ei[e];
        unsigned dst = (unsigned)ei[E + e];
        if (dst < (unsigned)n && src < (unsigned)n) {
            int pos = atomicAdd(&g_cursor[dst], 1);
            g_col[pos] = (int)src;
        }
    }
}

__global__ void k_pack_w(const float* __restrict__ W1l, const float* __restrict__ W1r,
                         const float* __restrict__ W2l, const float* __restrict__ W2r) {
    int t = blockIdx.x * blockDim.x + threadIdx.x;
    if (t < 64 * 128)            g_W1c[t] = W1l[t];
    else if (t < 128 * 128)      g_W1c[t] = W1r[t - 64 * 128];
    if (t < 32 * 64)             g_W2c[t] = W2l[t];
    else if (t < 64 * 64)        g_W2c[t] = W2r[t - 32 * 64];
}

// ---------------- bf16-split HMMA GEMM: C[M,N] = A[M,K] @ B[N,K]^T -----------
// 3-term compensation: Ah*Bh + Ah*Bl + Al*Bh, fp32 accumulate.
// CTA: 128 rows x N cols, 8 warps laid out 4(m) x 2(n). 256 threads.
template <int LAYER, int N, int K>
__global__ void __launch_bounds__(256, 1) gemm_mma(const float* __restrict__ A_ext, int M) {
    extern __shared__ __nv_bfloat16 sm[];
    constexpr int AS = K + 8;             // padded row stride (elements)
    constexpr int NT = (N / 2) / 8;       // B n-tiles per warp

    const float* __restrict__ A  = (LAYER == 1) ? A_ext : g_h;
    const float* __restrict__ Bw = (LAYER == 1) ? g_W1c : g_W2c;
    float* __restrict__ C        = (LAYER == 1) ? g_yz1 : g_yz2;

    __nv_bfloat16* Ah = sm;
    __nv_bfloat16* Al = sm + 128 * AS;
    __nv_bfloat16* Bh = sm + 2 * 128 * AS;
    __nv_bfloat16* Bl = Bh + N * AS;

    const int tid = threadIdx.x;
    const int bm0 = blockIdx.x * 128;

    // ---- convert fp32 -> bf16 hi/lo, store to padded SMEM tiles ----
#pragma unroll
    for (int i = tid; i < 128 * (K / 4); i += 256) {
        int r = i / (K / 4);
        int c = (i % (K / 4)) * 4;
        int grow = bm0 + r;
        float4 v = (grow < M) ? *(const float4*)(A + (size_t)grow * K + c)
                              : make_float4(0.f, 0.f, 0.f, 0.f);
        uint32_t l0, l1;
        uint32_t h0 = pack_hilo(v.x, v.y, l0);
        uint32_t h1 = pack_hilo(v.z, v.w, l1);
        int off = r * AS + c;
        *(uint32_t*)(Ah + off)     = h0;
        *(uint32_t*)(Ah + off + 2) = h1;
        *(uint32_t*)(Al + off)     = l0;
        *(uint32_t*)(Al + off + 2) = l1;
    }
#pragma unroll
    for (int i = tid; i < N * (K / 4); i += 256) {
        int r = i / (K / 4);
        int c = (i % (K / 4)) * 4;
        float4 v = *(const float4*)(Bw + (size_t)r * K + c);
        uint32_t l0, l1;
        uint32_t h0 = pack_hilo(v.x, v.y, l0);
        uint32_t h1 = pack_hilo(v.z, v.w, l1);
        int off = r * AS + c;
        *(uint32_t*)(Bh + off)     = h0;
        *(uint32_t*)(Bh + off + 2) = h1;
        *(uint32_t*)(Bl + off)     = l0;
        *(uint32_t*)(Bl + off + 2) = l1;
    }
    __syncthreads();

    const int wid = tid >> 5, lane = tid & 31;
    const int m0 = (wid >> 1) * 32;           // warp covers 32 rows
    const int n0 = (wid & 1) * (N / 2);       // and N/2 cols

    float acc[2][NT][4];
#pragma unroll
    for (int mi = 0; mi < 2; mi++)
#pragma unroll
        for (int ni = 0; ni < NT; ni++)
#pragma unroll
            for (int j = 0; j < 4; j++) acc[mi][ni][j] = 0.f;

    // precomputed per-lane offsets (elements)
    const int a_r = lane & 15, a_c = (lane >> 4) * 8;
    const int b_r = lane & 7,  b_c = ((lane >> 3) & 1) * 8;

#pragma unroll
    for (int t = 0; t < 3; t++) {
        const __nv_bfloat16* Ab = (t == 2) ? Al : Ah;
        const __nv_bfloat16* Bb = (t == 1) ? Bl : Bh;
        const uint32_t abase = smem_u32(Ab);
        const uint32_t bbase = smem_u32(Bb);
#pragma unroll
        for (int k0 = 0; k0 < K; k0 += 16) {
            uint32_t a[2][4], b[NT][2];
#pragma unroll
            for (int mi = 0; mi < 2; mi++) {
                uint32_t addr = abase + (uint32_t)(((m0 + mi * 16 + a_r) * AS + k0 + a_c) * 2);
                LDSM_X4(a[mi][0], a[mi][1], a[mi][2], a[mi][3], addr);
            }
#pragma unroll
            for (int ni = 0; ni < NT; ni++) {
                uint32_t addr = bbase + (uint32_t)(((n0 + ni * 8 + b_r) * AS + k0 + b_c) * 2);
                LDSM_X2(b[ni][0], b[ni][1], addr);
            }
#pragma unroll
            for (int mi = 0; mi < 2; mi++)
#pragma unroll
                for (int ni = 0; ni < NT; ni++)
                    MMA_BF16(acc[mi][ni], a[mi][0], a[mi][1], a[mi][2], a[mi][3],
                             b[ni][0], b[ni][1]);
        }
    }

    // ---- epilogue: mma C layout -> global ----
    const int erow = lane >> 2;             // 0..7
    const int ecol = (lane & 3) * 2;
#pragma unroll
    for (int mi = 0; mi < 2; mi++) {
#pragma unroll
        for (int ni = 0; ni < NT; ni++) {
            int col = n0 + ni * 8 + ecol;
            int r0 = bm0 + m0 + mi * 16 + erow;
            int r1 = r0 + 8;
            if (r0 < M)
                *(float2*)(C + (size_t)r0 * N + col) = make_float2(acc[mi][ni][0], acc[mi][ni][1]);
            if (r1 < M)
                *(float2*)(C + (size_t)r1 * N + col) = make_float2(acc[mi][ni][2], acc[mi][ni][3]);
        }
    }
}

// ---------------- layer 1 aggregation + relu ----------------
__global__ void k_agg1(const float* __restrict__ b1, int n) {
    int warp = (blockIdx.x * blockDim.x + threadIdx.x) >> 5;
    int lane = threadIdx.x & 31;
    if (warp >= n) return;
    int e0 = g_row_ptr[warp];
    int e1 = g_row_ptr[warp + 1];
    float a0 = 0.f, a1 = 0.f;
    for (int e = e0; e < e1; e++) {
        int s = g_col[e];
        const float* r = g_yz1 + (size_t)s * 128;
        a0 += r[lane];
        a1 += r[lane + 32];
    }
    float di = g_dinv[warp];
    const float* self = g_yz1 + (size_t)warp * 128;
    float v0 = a0 * di + b1[lane]      + self[64 + lane];
    float v1 = a1 * di + b1[lane + 32] + self[96 + lane];
    g_h[(size_t)warp * 64 + lane]      = fmaxf(v0, 0.f);
    g_h[(size_t)warp * 64 + lane + 32] = fmaxf(v1, 0.f);
}

// ---------------- layer 2 aggregation + log_softmax ----------------
__global__ void k_agg2(const float* __restrict__ b2, float* __restrict__ out, int n) {
    int warp = (blockIdx.x * blockDim.x + threadIdx.x) >> 5;
    int lane = threadIdx.x & 31;
    if (warp >= n) return;
    int e0 = g_row_ptr[warp];
    int e1 = g_row_ptr[warp + 1];
    float a = 0.f;
    for (int e = e0; e < e1; e++) {
        int s = g_col[e];
        a += g_yz2[(size_t)s * 64 + lane];
    }
    float di = g_dinv[warp];
    float val = a * di + b2[lane] + g_yz2[(size_t)warp * 64 + 32 + lane];

    float m = val;
#pragma unroll
    for (int off = 16; off >= 1; off >>= 1) m = fmaxf(m, __shfl_xor_sync(0xffffffffu, m, off));
    float ex = __expf(val - m);
    float s = ex;
#pragma unroll
    for (int off = 16; off >= 1; off >>= 1) s += __shfl_xor_sync(0xffffffffu, s, off);
    out[(size_t)warp * 32 + lane] = val - m - logf(s);
}

// ---------------- launch ----------------
extern "C" void kernel_launch(void* const* d_in, const int* in_sizes, int n_in,
                              void* d_out, int out_size) {
    const float* x   = (const float*)d_in[0];
    const int*   ei  = (const int*)d_in[1];
    const float* W1l = (const float*)d_in[2];
    const float* b1  = (const float*)d_in[3];
    const float* W1r = (const float*)d_in[4];
    const float* W2l = (const float*)d_in[5];
    const float* b2  = (const float*)d_in[6];
    const float* W2r = (const float*)d_in[7];
    float*       out = (float*)d_out;

    const int n = in_sizes[0] / D_IN;       // 100000
    const int E = in_sizes[1] / 2;          // 1600000

    // CSR build
    k_zero_deg<<<(n + 255) / 256, 256>>>(n);
    k_deg<<<(E + 255) / 256, 256>>>(ei, E, n);
    int scan_blocks = (n + 511) / 512;
    k_scan_a<<<scan_blocks, 512>>>(n);
    k_scan_b<<<1, 512>>>(scan_blocks);
    k_scan_c<<<scan_blocks, 512>>>(n, E);
    k_fill<<<(E + 255) / 256, 256>>>(ei, E, n);
    k_pack_w<<<(128 * 128 + 255) / 256, 256>>>(W1l, W1r, W2l, W2r);

    // SMEM: (Ah+Al) 2*128*(K+8) + (Bh+Bl) 2*N*(K+8), bf16 elements
    const int smem1 = (2 * 128 * (128 + 8) + 2 * 128 * (128 + 8)) * 2;   // 139264
    const int smem2 = (2 * 128 * (64 + 8)  + 2 * 64  * (64 + 8)) * 2;    // 55296
    static bool attr_set = false;
    if (!attr_set) {
        cudaFuncSetAttribute(gemm_mma<1, 128, 128>, cudaFuncAttributeMaxDynamicSharedMemorySize, smem1);
        cudaFuncSetAttribute(gemm_mma<2, 64, 64>,   cudaFuncAttributeMaxDynamicSharedMemorySize, smem2);
        attr_set = true;
    }

    int mtiles = (n + 127) / 128;

    // GEMM 1: yz1 = x @ [W1_l;W1_r]^T
    gemm_mma<1, 128, 128><<<mtiles, 256, smem1>>>(x, n);

    // agg + relu -> h
    k_agg1<<<(n * 32 + 255) / 256, 256>>>(b1, n);

    // GEMM 2: yz2 = h @ [W2_l;W2_r]^T
    gemm_mma<2, 64, 64><<<mtiles, 256, smem2>>>(nullptr, n);

    // agg + log_softmax -> out
    k_agg2<<<(n * 32 + 255) / 256, 256>>>(b2, out, n);
}

// round 6
// speedup vs baseline: 1.7859x; 1.0658x over previous
#include <cuda_runtime.h>
#include <cuda_bf16.h>
#include <math.h>
#include <stdint.h>

#define NN 100000
#define EE 1600000
#define D_IN 128
#define D_H  64
#define D_OUT 32

// ---------------- device scratch ----------------
__device__ int   g_deg[NN];
__device__ int   g_row_ptr[NN];
__device__ int   g_cursor[NN];
__device__ int   g_col[EE];
__device__ float g_dinv[NN];
__device__ int   g_total;

__device__ float g_yz1[(size_t)NN * 128];
__device__ float g_h  [(size_t)NN * 64];
__device__ float g_yz2[(size_t)NN * 64];

// ---------------- PTX helpers (base-arch only) ----------------
__device__ __forceinline__ uint32_t smem_u32(const void* p) {
    uint32_t a;
    asm("{ .reg .u64 t; cvta.to.shared.u64 t, %1; cvt.u32.u64 %0, t; }" : "=r"(a) : "l"(p));
    return a;
}

#define LDSM_X4(r0, r1, r2, r3, addr) \
    asm volatile("ldmatrix.sync.aligned.m8n8.x4.shared.b16 {%0,%1,%2,%3}, [%4];" \
                 : "=r"(r0), "=r"(r1), "=r"(r2), "=r"(r3) : "r"(addr))
#define LDSM_X2(r0, r1, addr) \
    asm volatile("ldmatrix.sync.aligned.m8n8.x2.shared.b16 {%0,%1}, [%2];" \
                 : "=r"(r0), "=r"(r1) : "r"(addr))
#define MMA_BF16(c, a0, a1, a2, a3, b0, b1) \
    asm volatile("mma.sync.aligned.m16n8k16.row.col.f32.bf16.bf16.f32 " \
                 "{%0,%1,%2,%3}, {%4,%5,%6,%7}, {%8,%9}, {%0,%1,%2,%3};" \
                 : "+f"((c)[0]), "+f"((c)[1]), "+f"((c)[2]), "+f"((c)[3]) \
                 : "r"(a0), "r"(a1), "r"(a2), "r"(a3), "r"(b0), "r"(b1))

__device__ __forceinline__ uint32_t pack_hilo(float a, float b, uint32_t& lo_out) {
    __nv_bfloat16 ha = __float2bfloat16(a), hb = __float2bfloat16(b);
    __nv_bfloat16 la = __float2bfloat16(a - __bfloat162float(ha));
    __nv_bfloat16 lb = __float2bfloat16(b - __bfloat162float(hb));
    __nv_bfloat162 h; h.x = ha; h.y = hb;
    __nv_bfloat162 l; l.x = la; l.y = lb;
    lo_out = *(uint32_t*)&l;
    return *(uint32_t*)&h;
}

// ---------------- CSR build (no prefix scan) ----------------
__global__ void k_zero_deg(int n) {
    int i = blockIdx.x * blockDim.x + threadIdx.x;
    if (i < n) g_deg[i] = 0;
    if (i == 0) g_total = 0;
}

__global__ void k_deg4(const int4* __restrict__ dst4, int E4, int n) {
    int i = blockIdx.x * blockDim.x + threadIdx.x;
    if (i < E4) {
        int4 d = dst4[i];
        if ((unsigned)d.x < (unsigned)n) atomicAdd(&g_deg[d.x], 1);
        if ((unsigned)d.y < (unsigned)n) atomicAdd(&g_deg[d.y], 1);
        if ((unsigned)d.z < (unsigned)n) atomicAdd(&g_deg[d.z], 1);
        if ((unsigned)d.w < (unsigned)n) atomicAdd(&g_deg[d.w], 1);
    }
}

// per-node segment allocation via global counter (order irrelevant for CSR)
__global__ void k_alloc(int n) {
    int i = blockIdx.x * blockDim.x + threadIdx.x;
    if (i < n) {
        int d = g_deg[i];
        int base = atomicAdd(&g_total, d);
        g_row_ptr[i] = base;
        g_cursor[i]  = base;
        g_dinv[i] = 1.0f / fmaxf((float)d, 1.0f);
    }
}

__global__ void k_fill4(const int4* __restrict__ src4, const int4* __restrict__ dst4,
                        int E4, int n) {
    int i = blockIdx.x * blockDim.x + threadIdx.x;
    if (i < E4) {
        int4 s = src4[i];
        int4 d = dst4[i];
        if ((unsigned)d.x < (unsigned)n && (unsigned)s.x < (unsigned)n)
            g_col[atomicAdd(&g_cursor[d.x], 1)] = s.x;
        if ((unsigned)d.y < (unsigned)n && (unsigned)s.y < (unsigned)n)
            g_col[atomicAdd(&g_cursor[d.y], 1)] = s.y;
        if ((unsigned)d.z < (unsigned)n && (unsigned)s.z < (unsigned)n)
            g_col[atomicAdd(&g_cursor[d.z], 1)] = s.z;
        if ((unsigned)d.w < (unsigned)n && (unsigned)s.w < (unsigned)n)
            g_col[atomicAdd(&g_cursor[d.w], 1)] = s.w;
    }
}

// ---------------- bf16-split HMMA GEMM: C[M,N] = A[M,K] @ [Wl;Wr][N,K]^T ----
template <int LAYER, int N, int K>
__global__ void __launch_bounds__(256, 1) gemm_mma(const float* __restrict__ A_ext,
                                                   const float* __restrict__ Wl,
                                                   const float* __restrict__ Wr, int M) {
    extern __shared__ __nv_bfloat16 sm[];
    constexpr int AS = K + 8;
    constexpr int NT = (N / 2) / 8;

    const float* __restrict__ A = (LAYER == 1) ? A_ext : g_h;
    float* __restrict__ C       = (LAYER == 1) ? g_yz1 : g_yz2;

    __nv_bfloat16* Ah = sm;
    __nv_bfloat16* Al = sm + 128 * AS;
    __nv_bfloat16* Bh = sm + 2 * 128 * AS;
    __nv_bfloat16* Bl = Bh + N * AS;

    const int tid = threadIdx.x;
    const int bm0 = blockIdx.x * 128;

#pragma unroll
    for (int i = tid; i < 128 * (K / 4); i += 256) {
        int r = i / (K / 4);
        int c = (i % (K / 4)) * 4;
        int grow = bm0 + r;
        float4 v = (grow < M) ? *(const float4*)(A + (size_t)grow * K + c)
                              : make_float4(0.f, 0.f, 0.f, 0.f);
        uint32_t l0, l1;
        uint32_t h0 = pack_hilo(v.x, v.y, l0);
        uint32_t h1 = pack_hilo(v.z, v.w, l1);
        int off = r * AS + c;
        *(uint32_t*)(Ah + off)     = h0;
        *(uint32_t*)(Ah + off + 2) = h1;
        *(uint32_t*)(Al + off)     = l0;
        *(uint32_t*)(Al + off + 2) = l1;
    }
#pragma unroll
    for (int i = tid; i < N * (K / 4); i += 256) {
        int r = i / (K / 4);
        int c = (i % (K / 4)) * 4;
        const float* src = (r < N / 2) ? (Wl + (size_t)r * K) : (Wr + (size_t)(r - N / 2) * K);
        float4 v = *(const float4*)(src + c);
        uint32_t l0, l1;
        uint32_t h0 = pack_hilo(v.x, v.y, l0);
        uint32_t h1 = pack_hilo(v.z, v.w, l1);
        int off = r * AS + c;
        *(uint32_t*)(Bh + off)     = h0;
        *(uint32_t*)(Bh + off + 2) = h1;
        *(uint32_t*)(Bl + off)     = l0;
        *(uint32_t*)(Bl + off + 2) = l1;
    }
    __syncthreads();

    const int wid = tid >> 5, lane = tid & 31;
    const int m0 = (wid >> 1) * 32;
    const int n0 = (wid & 1) * (N / 2);

    float acc[2][NT][4];
#pragma unroll
    for (int mi = 0; mi < 2; mi++)
#pragma unroll
        for (int ni = 0; ni < NT; ni++)
#pragma unroll
            for (int j = 0; j < 4; j++) acc[mi][ni][j] = 0.f;

    const int a_r = lane & 15, a_c = (lane >> 4) * 8;
    const int b_r = lane & 7,  b_c = ((lane >> 3) & 1) * 8;

#pragma unroll
    for (int t = 0; t < 3; t++) {
        const __nv_bfloat16* Ab = (t == 2) ? Al : Ah;
        const __nv_bfloat16* Bb = (t == 1) ? Bl : Bh;
        const uint32_t abase = smem_u32(Ab);
        const uint32_t bbase = smem_u32(Bb);
#pragma unroll
        for (int k0 = 0; k0 < K; k0 += 16) {
            uint32_t a[2][4], b[NT][2];
#pragma unroll
            for (int mi = 0; mi < 2; mi++) {
                uint32_t addr = abase + (uint32_t)(((m0 + mi * 16 + a_r) * AS + k0 + a_c) * 2);
                LDSM_X4(a[mi][0], a[mi][1], a[mi][2], a[mi][3], addr);
            }
#pragma unroll
            for (int ni = 0; ni < NT; ni++) {
                uint32_t addr = bbase + (uint32_t)(((n0 + ni * 8 + b_r) * AS + k0 + b_c) * 2);
                LDSM_X2(b[ni][0], b[ni][1], addr);
            }
#pragma unroll
            for (int mi = 0; mi < 2; mi++)
#pragma unroll
                for (int ni = 0; ni < NT; ni++)
                    MMA_BF16(acc[mi][ni], a[mi][0], a[mi][1], a[mi][2], a[mi][3],
                             b[ni][0], b[ni][1]);
        }
    }

    const int erow = lane >> 2;
    const int ecol = (lane & 3) * 2;
#pragma unroll
    for (int mi = 0; mi < 2; mi++) {
#pragma unroll
        for (int ni = 0; ni < NT; ni++) {
            int col = n0 + ni * 8 + ecol;
            int r0 = bm0 + m0 + mi * 16 + erow;
            int r1 = r0 + 8;
            if (r0 < M)
                *(float2*)(C + (size_t)r0 * N + col) = make_float2(acc[mi][ni][0], acc[mi][ni][1]);
            if (r1 < M)
                *(float2*)(C + (size_t)r1 * N + col) = make_float2(acc[mi][ni][2], acc[mi][ni][3]);
        }
    }
}

// ---------------- layer 1 aggregation + relu ----------------
__global__ void k_agg1(const float* __restrict__ b1, int n) {
    int warp = (blockIdx.x * blockDim.x + threadIdx.x) >> 5;
    int lane = threadIdx.x & 31;
    if (warp >= n) return;
    int e0 = g_row_ptr[warp];
    int e1 = e0 + g_deg[warp];
    float a0 = 0.f, a1 = 0.f;
    int e = e0;
    for (; e + 2 <= e1; e += 2) {
        int s0 = g_col[e], s1 = g_col[e + 1];
        const float* r0 = g_yz1 + (size_t)s0 * 128;
        const float* r1 = g_yz1 + (size_t)s1 * 128;
        float u0 = r0[lane], u1 = r0[lane + 32];
        float v0 = r1[lane], v1 = r1[lane + 32];
        a0 += u0 + v0;
        a1 += u1 + v1;
    }
    if (e < e1) {
        const float* r = g_yz1 + (size_t)g_col[e] * 128;
        a0 += r[lane];
        a1 += r[lane + 32];
    }
    float di = g_dinv[warp];
    const float* self = g_yz1 + (size_t)warp * 128;
    float v0 = a0 * di + b1[lane]      + self[64 + lane];
    float v1 = a1 * di + b1[lane + 32] + self[96 + lane];
    g_h[(size_t)warp * 64 + lane]      = fmaxf(v0, 0.f);
    g_h[(size_t)warp * 64 + lane + 32] = fmaxf(v1, 0.f);
}

// ---------------- layer 2 aggregation + log_softmax ----------------
__global__ void k_agg2(const float* __restrict__ b2, float* __restrict__ out, int n) {
    int warp = (blockIdx.x * blockDim.x + threadIdx.x) >> 5;
    int lane = threadIdx.x & 31;
    if (warp >= n) return;
    int e0 = g_row_ptr[warp];
    int e1 = e0 + g_deg[warp];
    float a = 0.f;
    int e = e0;
    for (; e + 2 <= e1; e += 2) {
        int s0 = g_col[e], s1 = g_col[e + 1];
        float u = g_yz2[(size_t)s0 * 64 + lane];
        float v = g_yz2[(size_t)s1 * 64 + lane];
        a += u + v;
    }
    if (e < e1) a += g_yz2[(size_t)g_col[e] * 64 + lane];

    float di = g_dinv[warp];
    float val = a * di + b2[lane] + g_yz2[(size_t)warp * 64 + 32 + lane];

    float m = val;
#pragma unroll
    for (int off = 16; off >= 1; off >>= 1) m = fmaxf(m, __shfl_xor_sync(0xffffffffu, m, off));
    float ex = __expf(val - m);
    float s = ex;
#pragma unroll
    for (int off = 16; off >= 1; off >>= 1) s += __shfl_xor_sync(0xffffffffu, s, off);
    out[(size_t)warp * 32 + lane] = val - m - logf(s);
}

// ---------------- launch ----------------
extern "C" void kernel_launch(void* const* d_in, const int* in_sizes, int n_in,
                              void* d_out, int out_size) {
    const float* x   = (const float*)d_in[0];
    const int*   ei  = (const int*)d_in[1];
    const float* W1l = (const float*)d_in[2];
    const float* b1  = (const float*)d_in[3];
    const float* W1r = (const float*)d_in[4];
    const float* W2l = (const float*)d_in[5];
    const float* b2  = (const float*)d_in[6];
    const float* W2r = (const float*)d_in[7];
    float*       out = (float*)d_out;

    const int n = in_sizes[0] / D_IN;       // 100000
    const int E = in_sizes[1] / 2;          // 1600000
    const int E4 = E / 4;

    const int smem1 = (2 * 128 * (128 + 8) + 2 * 128 * (128 + 8)) * 2;   // 139264
    const int smem2 = (2 * 128 * (64 + 8)  + 2 * 64  * (64 + 8)) * 2;    // 55296

    static cudaStream_t s1 = nullptr;
    static cudaEvent_t ev_fork = nullptr, ev_join = nullptr;
    static bool init_done = false;
    if (!init_done) {
        cudaFuncSetAttribute(gemm_mma<1, 128, 128>, cudaFuncAttributeMaxDynamicSharedMemorySize, smem1);
        cudaFuncSetAttribute(gemm_mma<2, 64, 64>,   cudaFuncAttributeMaxDynamicSharedMemorySize, smem2);
        cudaStreamCreateWithFlags(&s1, cudaStreamNonBlocking);
        cudaEventCreateWithFlags(&ev_fork, cudaEventDisableTiming);
        cudaEventCreateWithFlags(&ev_join, cudaEventDisableTiming);
        init_done = true;
    }

    const int4* src4 = (const int4*)ei;
    const int4* dst4 = (const int4*)(ei + E);

    // ---- fork: CSR build on s1, GEMM1 on main stream ----
    cudaEventRecord(ev_fork, 0);
    cudaStreamWaitEvent(s1, ev_fork, 0);

    k_zero_deg<<<(n + 255) / 256, 256, 0, s1>>>(n);
    k_deg4<<<(E4 + 255) / 256, 256, 0, s1>>>(dst4, E4, n);
    k_alloc<<<(n + 255) / 256, 256, 0, s1>>>(n);
    k_fill4<<<(E4 + 255) / 256, 256, 0, s1>>>(src4, dst4, E4, n);
    cudaEventRecord(ev_join, s1);

    int mtiles = (n + 127) / 128;
    gemm_mma<1, 128, 128><<<mtiles, 256, smem1>>>(x, W1l, W1r, n);

    // ---- join, then the dependent chain ----
    cudaStreamWaitEvent(0, ev_join, 0);
    k_agg1<<<(n * 32 + 255) / 256, 256>>>(b1, n);
    gemm_mma<2, 64, 64><<<mtiles, 256, smem2>>>(nullptr, W2l, W2r, n);
    k_agg2<<<(n * 32 + 255) / 256, 256>>>(b2, out, n);
}